// round 10
// baseline (speedup 1.0000x reference)
#include <cuda_runtime.h>
#include <cuda_bf16.h>
#include <cstdint>
#include <cstddef>

#define N_NODES 100000
#define N_EDGES 600000
#define HD 128
#define TILE_M 64
#define GTILES ((N_NODES + TILE_M - 1) / TILE_M)   // 1563
#define GEMM_CTAS 296
#define SCAN_CHUNK 1024
#define NBLK ((N_NODES + SCAN_CHUNK - 1) / SCAN_CHUNK)   // 98

// ---- scratch (allocation-free) ----
__device__ float g_M[(size_t)N_NODES * HD];
__device__ float g_H[(size_t)N_NODES * HD];
__device__ int   g_deg[N_NODES];
__device__ int   g_rowptr[N_NODES];
__device__ int   g_cursor[N_NODES];
__device__ int   g_ssrc[N_EDGES];
__device__ int   g_partials[NBLK];
__device__ __nv_bfloat16 g_W1hi[HD * HD];
__device__ __nv_bfloat16 g_W1lo[HD * HD];
__device__ __nv_bfloat16 g_W2hi[HD * HD];
__device__ __nv_bfloat16 g_W2lo[HD * HD];

__device__ __forceinline__ float leaky(float x) { return x > 0.f ? x : 0.2f * x; }

__device__ __forceinline__ uint32_t smem_u32(const void* p) {
    uint32_t a;
    asm("{ .reg .u64 t; cvta.to.shared.u64 t, %1; cvt.u32.u64 %0, t; }" : "=r"(a) : "l"(p));
    return a;
}
// pack two f32 -> bf16x2 (round-to-nearest), first arg in LOW half
__device__ __forceinline__ uint32_t cvt_bf2(float lo_half, float hi_half) {
    uint32_t r;
    asm("cvt.rn.bf16x2.f32 %0, %1, %2;" : "=r"(r) : "f"(hi_half), "f"(lo_half));
    return r;
}
// D += A * B  (m16n8k16 bf16->f32) — plain sm_80 PTX
__device__ __forceinline__ void mma16816(float* d, const uint32_t* a, uint32_t b0, uint32_t b1) {
    asm volatile(
        "mma.sync.aligned.m16n8k16.row.col.f32.bf16.bf16.f32 "
        "{%0,%1,%2,%3}, {%4,%5,%6,%7}, {%8,%9}, {%0,%1,%2,%3};"
        : "+f"(d[0]), "+f"(d[1]), "+f"(d[2]), "+f"(d[3])
        : "r"(a[0]), "r"(a[1]), "r"(a[2]), "r"(a[3]), "r"(b0), "r"(b1));
}
__device__ __forceinline__ void ldsm4(uint32_t* r, uint32_t addr) {
    asm volatile("ldmatrix.sync.aligned.m8n8.x4.shared.b16 {%0,%1,%2,%3}, [%4];"
                 : "=r"(r[0]), "=r"(r[1]), "=r"(r[2]), "=r"(r[3]) : "r"(addr));
}

// ================= W^T hi/lo prep (both layers, one launch) =================
__global__ void prep_wt_kernel(const float* __restrict__ W1,
                               const float* __restrict__ W2,
                               __nv_bfloat16* __restrict__ w1hi,
                               __nv_bfloat16* __restrict__ w1lo,
                               __nv_bfloat16* __restrict__ w2hi,
                               __nv_bfloat16* __restrict__ w2lo) {
    int gid = blockIdx.x * 256 + threadIdx.x;
    int which = gid >= HD * HD;
    int idx = gid - which * HD * HD;
    if (idx >= HD * HD) return;
    const float* W = which ? W2 : W1;
    __nv_bfloat16* whi = which ? w2hi : w1hi;
    __nv_bfloat16* wlo = which ? w2lo : w1lo;
    int n = idx >> 7, k = idx & 127;
    float x = W[k * HD + n];
    __nv_bfloat16 h = __float2bfloat16_rn(x);
    float r = x - __bfloat162float(h);
    whi[idx] = h;
    wlo[idx] = __float2bfloat16_rn(r);
}

// ================= persistent HMMA GEMM, 2 CTAs/SM, coalesced staging =======
// out[row,:] = (X[gather(row),:] @ W) * norm[row], split-bf16 3-product.
// SMEM per CTA: Bhi 32K | Blo 32K | Ahi 16K | Alo 16K = 96KB
#define SMB_BHI 0
#define SMB_BLO 32768
#define SMB_AHI 65536
#define SMB_ALO 81920
#define SM_TOTAL 98304

__global__ __launch_bounds__(256, 2)
void hmma_gemm_kernel(const float* __restrict__ X,
                      const int* __restrict__ idx,    // nullable
                      const __nv_bfloat16* __restrict__ wt_hi,
                      const __nv_bfloat16* __restrict__ wt_lo,
                      const float* __restrict__ norm,
                      float* __restrict__ out) {
    extern __shared__ char smem[];
    const uint32_t sb = smem_u32(smem);
    const int t = threadIdx.x;
    const int lane = t & 31, wid = t >> 5;

    // ---- load B hi/lo once (coalesced: half-warp per row, 512B/instr) ----
    {
        #pragma unroll
        for (int p = 0; p < 8; ++p) {
            const int r = wid * 16 + p * 2 + (lane >> 4);   // 0..127
            const int u = lane & 15;                        // uint4 chunk 0..15
            const uint32_t q = (uint32_t)u ^ (uint32_t)(r & 7);
            *reinterpret_cast<uint4*>(smem + SMB_BHI + r * 256 + q * 16) =
                __ldg(reinterpret_cast<const uint4*>(wt_hi + r * HD) + u);
            *reinterpret_cast<uint4*>(smem + SMB_BLO + r * 256 + q * 16) =
                __ldg(reinterpret_cast<const uint4*>(wt_lo + r * HD) + u);
        }
    }

    // ---- warp tiling: 8 warps = 2 row-groups x 4 col-groups; warp tile 32x32 ----
    const int wr = wid >> 2, wc = wid & 3;
    const int g = lane >> 2, tq = lane & 3;

    // ldmatrix lane mapping (validated rounds 7-9)
    const int sub = lane >> 3, subrow = lane & 7;
    const int cs = sub >> 1;            // k-chunk select
    const int s8 = (sub & 1) * 8;       // row half
    const int rB0 = wc * 32 + s8 + subrow;
    const int rB1 = rB0 + 16;
    const int rA0 = wr * 32 + s8 + subrow;
    const int rA1 = rA0 + 16;
    const uint32_t baB0 = rB0 * 256, r7B0 = rB0 & 7;
    const uint32_t baB1 = rB1 * 256, r7B1 = rB1 & 7;
    const uint32_t baA0 = rA0 * 256, r7A0 = rA0 & 7;
    const uint32_t baA1 = rA1 * 256, r7A1 = rA1 & 7;
    const uint32_t bHI = sb + SMB_BHI, bLO = sb + SMB_BLO;
    const uint32_t aHI = sb + SMB_AHI, aLO = sb + SMB_ALO;

    // A-stage swizzle constants (warp-per-row: lane l owns float4 #l = granules 2l,2l+1)
    const uint32_t achunk_base = (uint32_t)(lane >> 1);   // chunk before xor
    const uint32_t aoff_half = (uint32_t)(lane & 1) * 8;  // 8B half within 16B chunk

    for (int tile = blockIdx.x; tile < GTILES; tile += GEMM_CTAS) {
        const int row0 = tile * TILE_M;

        __syncthreads();   // prior tile's readers done (also orders first tile after B load)

        // ---- stage A (coalesced: one warp per row, one LDG.128 per lane) ----
        #pragma unroll
        for (int p = 0; p < 8; ++p) {
            const int r = wid * 8 + p;          // local row 0..63
            const int row = row0 + r;
            char* DH = smem + SMB_AHI + r * 256;
            char* DL = smem + SMB_ALO + r * 256;
            const uint32_t chunk = (achunk_base ^ (uint32_t)(r & 7)) * 16 + aoff_half;
            if (row < N_NODES) {
                const int srow = idx ? __ldg(idx + row) : row;
                float4 v = __ldg(reinterpret_cast<const float4*>(X + (size_t)srow * HD) + lane);
                uint32_t h0 = __byte_perm(__float_as_uint(v.x), __float_as_uint(v.y), 0x7632);
                uint32_t h1 = __byte_perm(__float_as_uint(v.z), __float_as_uint(v.w), 0x7632);
                uint32_t l0 = cvt_bf2(v.x - __uint_as_float(h0 << 16),
                                      v.y - __uint_as_float(h0 & 0xFFFF0000u));
                uint32_t l1 = cvt_bf2(v.z - __uint_as_float(h1 << 16),
                                      v.w - __uint_as_float(h1 & 0xFFFF0000u));
                *reinterpret_cast<uint2*>(DH + chunk) = make_uint2(h0, h1);
                *reinterpret_cast<uint2*>(DL + chunk) = make_uint2(l0, l1);
            } else {
                *reinterpret_cast<uint2*>(DH + chunk) = make_uint2(0u, 0u);
                *reinterpret_cast<uint2*>(DL + chunk) = make_uint2(0u, 0u);
            }
        }
        __syncthreads();

        // ---- compute: pure ldsm + mma ----
        float acc[2][4][4];
        #pragma unroll
        for (int mt = 0; mt < 2; ++mt)
            #pragma unroll
            for (int nt = 0; nt < 4; ++nt)
                #pragma unroll
                for (int c = 0; c < 4; ++c) acc[mt][nt][c] = 0.f;

        #pragma unroll
        for (int s = 0; s < 8; ++s) {
            const uint32_t ck = (uint32_t)(2 * s + cs);
            const uint32_t oA0 = baA0 + ((ck ^ r7A0) << 4);
            const uint32_t oA1 = baA1 + ((ck ^ r7A1) << 4);
            const uint32_t oB0 = baB0 + ((ck ^ r7B0) << 4);
            const uint32_t oB1 = baB1 + ((ck ^ r7B1) << 4);

            uint32_t ah0[4], al0[4], ah1[4], al1[4];
            uint32_t bh0[4], bl0[4], bh1[4], bl1[4];
            ldsm4(ah0, aHI + oA0); ldsm4(al0, aLO + oA0);
            ldsm4(ah1, aHI + oA1); ldsm4(al1, aLO + oA1);
            ldsm4(bh0, bHI + oB0); ldsm4(bl0, bLO + oB0);
            ldsm4(bh1, bHI + oB1); ldsm4(bl1, bLO + oB1);

            #pragma unroll
            for (int mt = 0; mt < 2; ++mt) {
                const uint32_t* ah = mt ? ah1 : ah0;
                const uint32_t* al = mt ? al1 : al0;
                mma16816(acc[mt][0], ah, bh0[0], bh0[2]);
                mma16816(acc[mt][0], ah, bl0[0], bl0[2]);
                mma16816(acc[mt][0], al, bh0[0], bh0[2]);
                mma16816(acc[mt][1], ah, bh0[1], bh0[3]);
                mma16816(acc[mt][1], ah, bl0[1], bl0[3]);
                mma16816(acc[mt][1], al, bh0[1], bh0[3]);
                mma16816(acc[mt][2], ah, bh1[0], bh1[2]);
                mma16816(acc[mt][2], ah, bl1[0], bl1[2]);
                mma16816(acc[mt][2], al, bh1[0], bh1[2]);
                mma16816(acc[mt][3], ah, bh1[1], bh1[3]);
                mma16816(acc[mt][3], ah, bl1[1], bl1[3]);
                mma16816(acc[mt][3], al, bh1[1], bh1[3]);
            }
        }

        // ---- epilogue: * norm, store f32 ----
        #pragma unroll
        for (int mt = 0; mt < 2; ++mt) {
            const int rA = row0 + wr * 32 + mt * 16 + g;
            const int rB = rA + 8;
            const bool okA = rA < N_NODES, okB = rB < N_NODES;
            const float sA = okA ? __ldg(norm + rA) : 0.f;
            const float sB = okB ? __ldg(norm + rB) : 0.f;
            #pragma unroll
            for (int nt = 0; nt < 4; ++nt) {
                const int col = wc * 32 + nt * 8 + tq * 2;
                if (okA) {
                    float2 v = make_float2(acc[mt][nt][0] * sA, acc[mt][nt][1] * sA);
                    *reinterpret_cast<float2*>(out + (size_t)rA * HD + col) = v;
                }
                if (okB) {
                    float2 v = make_float2(acc[mt][nt][2] * sB, acc[mt][nt][3] * sB);
                    *reinterpret_cast<float2*>(out + (size_t)rB * HD + col) = v;
                }
            }
        }
    }
}

// ================= CSR build =================

__global__ void hist_kernel(const int* __restrict__ dst, int* __restrict__ deg) {
    int e = blockIdx.x * 256 + threadIdx.x;
    if (e < N_EDGES) atomicAdd(&deg[dst[e]], 1);
}

__global__ void scan_block_kernel(const int* __restrict__ deg,
                                  int* __restrict__ rowptr,
                                  int* __restrict__ partials) {
    __shared__ int wsum[8];
    const int t = threadIdx.x;
    const int base = blockIdx.x * SCAN_CHUNK + t * 4;
    int v[4];
    #pragma unroll
    for (int j = 0; j < 4; ++j) {
        int i = base + j;
        v[j] = (i < N_NODES) ? deg[i] : 0;
    }
    int s = v[0] + v[1] + v[2] + v[3];
    const int lane = t & 31, wid = t >> 5;
    int x = s;
    #pragma unroll
    for (int o = 1; o < 32; o <<= 1) {
        int y = __shfl_up_sync(~0u, x, o);
        if (lane >= o) x += y;
    }
    if (lane == 31) wsum[wid] = x;
    __syncthreads();
    if (wid == 0) {
        int ws = (lane < 8) ? wsum[lane] : 0;
        #pragma unroll
        for (int o = 1; o < 8; o <<= 1) {
            int y = __shfl_up_sync(~0u, ws, o);
            if (lane >= o) ws += y;
        }
        if (lane < 8) wsum[lane] = ws;
    }
    __syncthreads();
    int run = (x - s) + (wid > 0 ? wsum[wid - 1] : 0);
    #pragma unroll
    for (int j = 0; j < 4; ++j) {
        int i = base + j;
        if (i < N_NODES) rowptr[i] = run;
        run += v[j];
    }
    if (t == 0) partials[blockIdx.x] = wsum[7];
}

__global__ void scan_partials_kernel(int* __restrict__ partials) {
    __shared__ int wsum[4];
    const int t = threadIdx.x;
    int v = (t < NBLK) ? partials[t] : 0;
    const int lane = t & 31, wid = t >> 5;
    int x = v;
    #pragma unroll
    for (int o = 1; o < 32; o <<= 1) {
        int y = __shfl_up_sync(~0u, x, o);
        if (lane >= o) x += y;
    }
    if (lane == 31) wsum[wid] = x;
    __syncthreads();
    if (t == 0) {
        int a = 0;
        #pragma unroll
        for (int w = 0; w < 4; ++w) { int s2 = wsum[w]; wsum[w] = a; a += s2; }
    }
    __syncthreads();
    int excl = (x - v) + wsum[wid];
    if (t < NBLK) partials[t] = excl;
}

__global__ void scan_add_kernel(int* __restrict__ rowptr,
                                const int* __restrict__ partials,
                                int* __restrict__ cursor) {
    int i = blockIdx.x * 256 + threadIdx.x;
    if (i < N_NODES) {
        int r = rowptr[i] + partials[i >> 10];
        rowptr[i] = r;
        cursor[i] = r;
    }
}

__global__ void permute_kernel(const int* __restrict__ src,
                               const int* __restrict__ dst,
                               int* __restrict__ cursor,
                               int* __restrict__ ssrc) {
    int e = blockIdx.x * 256 + threadIdx.x;
    if (e < N_EDGES) {
        int d = dst[e];
        int pos = atomicAdd(&cursor[d], 1);
        ssrc[pos] = src[e];
    }
}

// ================= load-balanced gather + fused epilogue (MLP-4) =================
#define GATHER_BLOCKS 512
__global__ void gather_kernel(const float* __restrict__ M,
                              const int* __restrict__ rowptr,
                              const int* __restrict__ deg,
                              const int* __restrict__ ssrc,
                              const float* __restrict__ norm,
                              const float* __restrict__ b,
                              float* __restrict__ out) {
    const int gw = blockIdx.x * 8 + (threadIdx.x >> 5);
    const int lane = threadIdx.x & 31;
    const int nwarps = GATHER_BLOCKS * 8;
    const float4 bb = __ldg(reinterpret_cast<const float4*>(b) + lane);

    for (int node = gw; node < N_NODES; node += nwarps) {
        const int start = __ldg(rowptr + node);
        const int d = __ldg(deg + node);
        float4 acc = make_float4(0.f, 0.f, 0.f, 0.f);
        int j = 0;
        for (; j + 4 <= d; j += 4) {
            int s0 = __ldg(ssrc + start + j + 0);
            int s1 = __ldg(ssrc + start + j + 1);
            int s2 = __ldg(ssrc + start + j + 2);
            int s3 = __ldg(ssrc + start + j + 3);
            float4 v0 = __ldg(reinterpret_cast<const float4*>(M + (size_t)s0 * HD) + lane);
            float4 v1 = __ldg(reinterpret_cast<const float4*>(M + (size_t)s1 * HD) + lane);
            float4 v2 = __ldg(reinterpret_cast<const float4*>(M + (size_t)s2 * HD) + lane);
            float4 v3 = __ldg(reinterpret_cast<const float4*>(M + (size_t)s3 * HD) + lane);
            acc.x += v0.x + v1.x + v2.x + v3.x;
            acc.y += v0.y + v1.y + v2.y + v3.y;
            acc.z += v0.z + v1.z + v2.z + v3.z;
            acc.w += v0.w + v1.w + v2.w + v3.w;
        }
        for (; j < d; ++j) {
            int s = __ldg(ssrc + start + j);
            float4 v = __ldg(reinterpret_cast<const float4*>(M + (size_t)s * HD) + lane);
            acc.x += v.x; acc.y += v.y; acc.z += v.z; acc.w += v.w;
        }
        const float sc = __ldg(norm + node);
        float4 n;
        n.x = leaky(acc.x * sc + bb.x);
        n.y = leaky(acc.y * sc + bb.y);
        n.z = leaky(acc.z * sc + bb.z);
        n.w = leaky(acc.w * sc + bb.w);
        reinterpret_cast<float4*>(out + (size_t)node * HD)[lane] = n;
    }
}

extern "C" void kernel_launch(void* const* d_in, const int* in_sizes, int n_in,
                              void* d_out, int out_size) {
    const int*   node_id = (const int*)d_in[0];
    const int*   src     = (const int*)d_in[1];
    const int*   dst     = (const int*)d_in[2];
    const float* norm    = (const float*)d_in[3];
    const float* embed   = (const float*)d_in[4];
    const float* W1      = (const float*)d_in[5];
    const float* b1      = (const float*)d_in[6];
    const float* W2      = (const float*)d_in[7];
    const float* b2      = (const float*)d_in[8];
    float* out = (float*)d_out;

    void *pM, *pH, *pDeg, *pRow, *pCur, *pSS, *pPart, *p1h, *p1l, *p2h, *p2l;
    cudaGetSymbolAddress(&pM, g_M);
    cudaGetSymbolAddress(&pH, g_H);
    cudaGetSymbolAddress(&pDeg, g_deg);
    cudaGetSymbolAddress(&pRow, g_rowptr);
    cudaGetSymbolAddress(&pCur, g_cursor);
    cudaGetSymbolAddress(&pSS, g_ssrc);
    cudaGetSymbolAddress(&pPart, g_partials);
    cudaGetSymbolAddress(&p1h, g_W1hi);
    cudaGetSymbolAddress(&p1l, g_W1lo);
    cudaGetSymbolAddress(&p2h, g_W2hi);
    cudaGetSymbolAddress(&p2l, g_W2lo);
    float* M = (float*)pM;
    float* H = (float*)pH;
    int *deg = (int*)pDeg, *rowptr = (int*)pRow, *cursor = (int*)pCur;
    int *ssrc = (int*)pSS, *partials = (int*)pPart;
    __nv_bfloat16 *w1hi = (__nv_bfloat16*)p1h, *w1lo = (__nv_bfloat16*)p1l;
    __nv_bfloat16 *w2hi = (__nv_bfloat16*)p2h, *w2lo = (__nv_bfloat16*)p2l;

    cudaFuncSetAttribute(hmma_gemm_kernel,
                         cudaFuncAttributeMaxDynamicSharedMemorySize, SM_TOTAL);

    const int edge_grid = (N_EDGES + 255) / 256;
    const int node_grid = (N_NODES + 255) / 256;
    const int wt_grid   = (2 * HD * HD + 255) / 256;

    // Launch order keeps the GEMM as the 4th non-memset kernel (ncu window).
    cudaMemsetAsync(deg, 0, N_NODES * sizeof(int));
    hist_kernel<<<edge_grid, 256>>>(dst, deg);
    scan_block_kernel<<<NBLK, 256>>>(deg, rowptr, partials);
    prep_wt_kernel<<<wt_grid, 256>>>(W1, W2, w1hi, w1lo, w2hi, w2lo);

    // ---- Layer 1 GEMM (embedding gather fused) ----
    hmma_gemm_kernel<<<GEMM_CTAS, 256, SM_TOTAL>>>(embed, node_id, w1hi, w1lo, norm, M);

    // CSR back-half:
    scan_partials_kernel<<<1, 128>>>(partials);
    scan_add_kernel<<<node_grid, 256>>>(rowptr, partials, cursor);
    permute_kernel<<<edge_grid, 256>>>(src, dst, cursor, ssrc);

    gather_kernel<<<GATHER_BLOCKS, 256>>>(M, rowptr, deg, ssrc, norm, b1, H);

    // ---- Layer 2 ----
    hmma_gemm_kernel<<<GEMM_CTAS, 256, SM_TOTAL>>>(H, nullptr, w2hi, w2lo, norm, M);
    gather_kernel<<<GATHER_BLOCKS, 256>>>(M, rowptr, deg, ssrc, norm, b2, out);
}

// round 11
// speedup vs baseline: 1.0783x; 1.0783x over previous
#include <cuda_runtime.h>
#include <cuda_bf16.h>
#include <cstdint>
#include <cstddef>

#define N_NODES 100000
#define N_EDGES 600000
#define HD 128
#define TILE_M 64
#define GTILES ((N_NODES + TILE_M - 1) / TILE_M)   // 1563
#define GEMM_CTAS 296
#define SCAN_CHUNK 1024
#define NBLK ((N_NODES + SCAN_CHUNK - 1) / SCAN_CHUNK)   // 98

// ---- scratch (allocation-free) ----
__device__ float g_M[(size_t)N_NODES * HD];
__device__ float g_H[(size_t)N_NODES * HD];
__device__ int   g_deg[N_NODES];
__device__ int   g_rowptr[N_NODES];
__device__ int   g_cursor[N_NODES];
__device__ int   g_ssrc[N_EDGES];
__device__ int   g_partials[NBLK];
__device__ __nv_bfloat16 g_W1hi[HD * HD];
__device__ __nv_bfloat16 g_W1lo[HD * HD];
__device__ __nv_bfloat16 g_W2hi[HD * HD];
__device__ __nv_bfloat16 g_W2lo[HD * HD];

__device__ __forceinline__ float leaky(float x) { return x > 0.f ? x : 0.2f * x; }

__device__ __forceinline__ uint32_t smem_u32(const void* p) {
    uint32_t a;
    asm("{ .reg .u64 t; cvta.to.shared.u64 t, %1; cvt.u32.u64 %0, t; }" : "=r"(a) : "l"(p));
    return a;
}
// pack two f32 -> bf16x2 (round-to-nearest), first arg in LOW half
__device__ __forceinline__ uint32_t cvt_bf2(float lo_half, float hi_half) {
    uint32_t r;
    asm("cvt.rn.bf16x2.f32 %0, %1, %2;" : "=r"(r) : "f"(hi_half), "f"(lo_half));
    return r;
}
// D += A * B  (m16n8k16 bf16->f32) — plain sm_80 PTX
__device__ __forceinline__ void mma16816(float* d, const uint32_t* a, uint32_t b0, uint32_t b1) {
    asm volatile(
        "mma.sync.aligned.m16n8k16.row.col.f32.bf16.bf16.f32 "
        "{%0,%1,%2,%3}, {%4,%5,%6,%7}, {%8,%9}, {%0,%1,%2,%3};"
        : "+f"(d[0]), "+f"(d[1]), "+f"(d[2]), "+f"(d[3])
        : "r"(a[0]), "r"(a[1]), "r"(a[2]), "r"(a[3]), "r"(b0), "r"(b1));
}
__device__ __forceinline__ void ldsm4(uint32_t* r, uint32_t addr) {
    asm volatile("ldmatrix.sync.aligned.m8n8.x4.shared.b16 {%0,%1,%2,%3}, [%4];"
                 : "=r"(r[0]), "=r"(r[1]), "=r"(r[2]), "=r"(r[3]) : "r"(addr));
}

// ================= W^T hi/lo prep (both layers, one launch) =================
__global__ void prep_wt_kernel(const float* __restrict__ W1,
                               const float* __restrict__ W2,
                               __nv_bfloat16* __restrict__ w1hi,
                               __nv_bfloat16* __restrict__ w1lo,
                               __nv_bfloat16* __restrict__ w2hi,
                               __nv_bfloat16* __restrict__ w2lo) {
    int gid = blockIdx.x * 256 + threadIdx.x;
    int which = gid >= HD * HD;
    int idx = gid - which * HD * HD;
    if (idx >= HD * HD) return;
    const float* W = which ? W2 : W1;
    __nv_bfloat16* whi = which ? w2hi : w1hi;
    __nv_bfloat16* wlo = which ? w2lo : w1lo;
    int n = idx >> 7, k = idx & 127;
    float x = W[k * HD + n];
    __nv_bfloat16 h = __float2bfloat16_rn(x);
    float r = x - __bfloat162float(h);
    whi[idx] = h;
    wlo[idx] = __float2bfloat16_rn(r);
}

// ================= persistent HMMA GEMM, 2 CTAs/SM, register-prefetch A =====
// out[row,:] = (X[gather(row),:] @ W) * norm[row], split-bf16 3-product.
// SMEM per CTA: Bhi 32K | Blo 32K | Ahi 16K | Alo 16K = 96KB
#define SMB_BHI 0
#define SMB_BLO 32768
#define SMB_AHI 65536
#define SMB_ALO 81920
#define SM_TOTAL 98304

__global__ __launch_bounds__(256, 2)
void hmma_gemm_kernel(const float* __restrict__ X,
                      const int* __restrict__ idx,    // nullable
                      const __nv_bfloat16* __restrict__ wt_hi,
                      const __nv_bfloat16* __restrict__ wt_lo,
                      const float* __restrict__ norm,
                      float* __restrict__ out) {
    extern __shared__ char smem[];
    const uint32_t sb = smem_u32(smem);
    const int t = threadIdx.x;
    const int lane = t & 31, wid = t >> 5;

    // ---- load B hi/lo once (coalesced: half-warp per row) ----
    {
        #pragma unroll
        for (int p = 0; p < 8; ++p) {
            const int r = wid * 16 + p * 2 + (lane >> 4);   // 0..127
            const int u = lane & 15;                        // uint4 chunk 0..15
            const uint32_t q = (uint32_t)u ^ (uint32_t)(r & 7);
            *reinterpret_cast<uint4*>(smem + SMB_BHI + r * 256 + q * 16) =
                __ldg(reinterpret_cast<const uint4*>(wt_hi + r * HD) + u);
            *reinterpret_cast<uint4*>(smem + SMB_BLO + r * 256 + q * 16) =
                __ldg(reinterpret_cast<const uint4*>(wt_lo + r * HD) + u);
        }
    }

    // ---- warp tiling: 8 warps = 2 row-groups x 4 col-groups; warp tile 32x32 ----
    const int wr = wid >> 2, wc = wid & 3;
    const int g = lane >> 2, tq = lane & 3;

    // ldmatrix lane mapping (validated rounds 7-10)
    const int sub = lane >> 3, subrow = lane & 7;
    const int cs = sub >> 1;
    const int s8 = (sub & 1) * 8;
    const int rB0 = wc * 32 + s8 + subrow;
    const int rB1 = rB0 + 16;
    const int rA0 = wr * 32 + s8 + subrow;
    const int rA1 = rA0 + 16;
    const uint32_t baB0 = rB0 * 256, r7B0 = rB0 & 7;
    const uint32_t baB1 = rB1 * 256, r7B1 = rB1 & 7;
    const uint32_t baA0 = rA0 * 256, r7A0 = rA0 & 7;
    const uint32_t baA1 = rA1 * 256, r7A1 = rA1 & 7;
    const uint32_t bHI = sb + SMB_BHI, bLO = sb + SMB_BLO;
    const uint32_t aHI = sb + SMB_AHI, aLO = sb + SMB_ALO;

    // A staging coords (round-9 high-MLP layout: 4 threads/row, 8 float4 each)
    const int sr_ = t >> 2;            // local row 0..63
    const int sq_ = t & 3;

    // register prefetch buffer: 8 float4 = 32 regs
    float4 pf[8];

    // issue LDGs for a tile's A slice into pf (8 independent loads after 1 idx load)
    auto load_tile = [&](int tile) {
        const int row = tile * TILE_M + sr_;
        if (row < N_NODES) {
            const int srow = idx ? __ldg(idx + row) : row;
            const float4* gsrc = reinterpret_cast<const float4*>(X + (size_t)srow * HD);
            #pragma unroll
            for (int j = 0; j < 8; ++j) pf[j] = __ldg(gsrc + sq_ * 8 + j);
        } else {
            #pragma unroll
            for (int j = 0; j < 8; ++j) pf[j] = make_float4(0.f, 0.f, 0.f, 0.f);
        }
    };
    // convert pf -> hi/lo bf16 and store swizzled
    auto sts_tile = [&]() {
        char* DH = smem + SMB_AHI + sr_ * 256;
        char* DL = smem + SMB_ALO + sr_ * 256;
        #pragma unroll
        for (int j = 0; j < 8; ++j) {
            const int c4 = sq_ * 8 + j;
            float4 v = pf[j];
            uint32_t h0 = __byte_perm(__float_as_uint(v.x), __float_as_uint(v.y), 0x7632);
            uint32_t h1 = __byte_perm(__float_as_uint(v.z), __float_as_uint(v.w), 0x7632);
            uint32_t l0 = cvt_bf2(v.x - __uint_as_float(h0 << 16),
                                  v.y - __uint_as_float(h0 & 0xFFFF0000u));
            uint32_t l1 = cvt_bf2(v.z - __uint_as_float(h1 << 16),
                                  v.w - __uint_as_float(h1 & 0xFFFF0000u));
            uint32_t chunk = ((uint32_t)(c4 >> 1)) ^ (uint32_t)(sr_ & 7);
            uint32_t off = chunk * 16 + ((uint32_t)(2 * c4) & 3) * 4;
            *reinterpret_cast<uint2*>(DH + off) = make_uint2(h0, h1);
            *reinterpret_cast<uint2*>(DL + off) = make_uint2(l0, l1);
        }
    };

    // tiles owned by this CTA
    int tiles[8];
    int ntl = 0;
    for (int tile = blockIdx.x; tile < GTILES; tile += GEMM_CTAS) tiles[ntl++] = tile;

    load_tile(tiles[0]);       // prefetch tile 0 (overlaps with B-load completion)

    for (int i = 0; i < ntl; ++i) {
        sts_tile();            // convert + store prefetched tile i
        __syncthreads();

        if (i + 1 < ntl) load_tile(tiles[i + 1]);   // LDGs in flight during compute

        const int row0 = tiles[i] * TILE_M;

        float acc[2][4][4];
        #pragma unroll
        for (int mt = 0; mt < 2; ++mt)
            #pragma unroll
            for (int nt = 0; nt < 4; ++nt)
                #pragma unroll
                for (int c = 0; c < 4; ++c) acc[mt][nt][c] = 0.f;

        #pragma unroll
        for (int s = 0; s < 8; ++s) {
            const uint32_t ck = (uint32_t)(2 * s + cs);
            const uint32_t oA0 = baA0 + ((ck ^ r7A0) << 4);
            const uint32_t oA1 = baA1 + ((ck ^ r7A1) << 4);
            const uint32_t oB0 = baB0 + ((ck ^ r7B0) << 4);
            const uint32_t oB1 = baB1 + ((ck ^ r7B1) << 4);

            uint32_t ah0[4], al0[4], ah1[4], al1[4];
            uint32_t bh0[4], bl0[4], bh1[4], bl1[4];
            ldsm4(ah0, aHI + oA0); ldsm4(al0, aLO + oA0);
            ldsm4(ah1, aHI + oA1); ldsm4(al1, aLO + oA1);
            ldsm4(bh0, bHI + oB0); ldsm4(bl0, bLO + oB0);
            ldsm4(bh1, bHI + oB1); ldsm4(bl1, bLO + oB1);

            #pragma unroll
            for (int mt = 0; mt < 2; ++mt) {
                const uint32_t* ah = mt ? ah1 : ah0;
                const uint32_t* al = mt ? al1 : al0;
                mma16816(acc[mt][0], ah, bh0[0], bh0[2]);
                mma16816(acc[mt][0], ah, bl0[0], bl0[2]);
                mma16816(acc[mt][0], al, bh0[0], bh0[2]);
                mma16816(acc[mt][1], ah, bh0[1], bh0[3]);
                mma16816(acc[mt][1], ah, bl0[1], bl0[3]);
                mma16816(acc[mt][1], al, bh0[1], bh0[3]);
                mma16816(acc[mt][2], ah, bh1[0], bh1[2]);
                mma16816(acc[mt][2], ah, bl1[0], bl1[2]);
                mma16816(acc[mt][2], al, bh1[0], bh1[2]);
                mma16816(acc[mt][3], ah, bh1[1], bh1[3]);
                mma16816(acc[mt][3], ah, bl1[1], bl1[3]);
                mma16816(acc[mt][3], al, bh1[1], bh1[3]);
            }
        }

        // ---- epilogue: * norm, store f32 ----
        #pragma unroll
        for (int mt = 0; mt < 2; ++mt) {
            const int rA = row0 + wr * 32 + mt * 16 + g;
            const int rB = rA + 8;
            const bool okA = rA < N_NODES, okB = rB < N_NODES;
            const float sA = okA ? __ldg(norm + rA) : 0.f;
            const float sB = okB ? __ldg(norm + rB) : 0.f;
            #pragma unroll
            for (int nt = 0; nt < 4; ++nt) {
                const int col = wc * 32 + nt * 8 + tq * 2;
                if (okA) {
                    float2 v = make_float2(acc[mt][nt][0] * sA, acc[mt][nt][1] * sA);
                    *reinterpret_cast<float2*>(out + (size_t)rA * HD + col) = v;
                }
                if (okB) {
                    float2 v = make_float2(acc[mt][nt][2] * sB, acc[mt][nt][3] * sB);
                    *reinterpret_cast<float2*>(out + (size_t)rB * HD + col) = v;
                }
            }
        }
        __syncthreads();   // readers done before next STS overwrites A
    }
}

// ================= CSR build =================

__global__ void hist_kernel(const int* __restrict__ dst, int* __restrict__ deg) {
    int e = blockIdx.x * 256 + threadIdx.x;
    if (e < N_EDGES) atomicAdd(&deg[dst[e]], 1);
}

__global__ void scan_block_kernel(const int* __restrict__ deg,
                                  int* __restrict__ rowptr,
                                  int* __restrict__ partials) {
    __shared__ int wsum[8];
    const int t = threadIdx.x;
    const int base = blockIdx.x * SCAN_CHUNK + t * 4;
    int v[4];
    #pragma unroll
    for (int j = 0; j < 4; ++j) {
        int i = base + j;
        v[j] = (i < N_NODES) ? deg[i] : 0;
    }
    int s = v[0] + v[1] + v[2] + v[3];
    const int lane = t & 31, wid = t >> 5;
    int x = s;
    #pragma unroll
    for (int o = 1; o < 32; o <<= 1) {
        int y = __shfl_up_sync(~0u, x, o);
        if (lane >= o) x += y;
    }
    if (lane == 31) wsum[wid] = x;
    __syncthreads();
    if (wid == 0) {
        int ws = (lane < 8) ? wsum[lane] : 0;
        #pragma unroll
        for (int o = 1; o < 8; o <<= 1) {
            int y = __shfl_up_sync(~0u, ws, o);
            if (lane >= o) ws += y;
        }
        if (lane < 8) wsum[lane] = ws;
    }
    __syncthreads();
    int run = (x - s) + (wid > 0 ? wsum[wid - 1] : 0);
    #pragma unroll
    for (int j = 0; j < 4; ++j) {
        int i = base + j;
        if (i < N_NODES) rowptr[i] = run;
        run += v[j];
    }
    if (t == 0) partials[blockIdx.x] = wsum[7];
}

__global__ void scan_partials_kernel(int* __restrict__ partials) {
    __shared__ int wsum[4];
    const int t = threadIdx.x;
    int v = (t < NBLK) ? partials[t] : 0;
    const int lane = t & 31, wid = t >> 5;
    int x = v;
    #pragma unroll
    for (int o = 1; o < 32; o <<= 1) {
        int y = __shfl_up_sync(~0u, x, o);
        if (lane >= o) x += y;
    }
    if (lane == 31) wsum[wid] = x;
    __syncthreads();
    if (t == 0) {
        int a = 0;
        #pragma unroll
        for (int w = 0; w < 4; ++w) { int s2 = wsum[w]; wsum[w] = a; a += s2; }
    }
    __syncthreads();
    int excl = (x - v) + wsum[wid];
    if (t < NBLK) partials[t] = excl;
}

__global__ void scan_add_kernel(int* __restrict__ rowptr,
                                const int* __restrict__ partials,
                                int* __restrict__ cursor) {
    int i = blockIdx.x * 256 + threadIdx.x;
    if (i < N_NODES) {
        int r = rowptr[i] + partials[i >> 10];
        rowptr[i] = r;
        cursor[i] = r;
    }
}

__global__ void permute_kernel(const int* __restrict__ src,
                               const int* __restrict__ dst,
                               int* __restrict__ cursor,
                               int* __restrict__ ssrc) {
    int e = blockIdx.x * 256 + threadIdx.x;
    if (e < N_EDGES) {
        int d = dst[e];
        int pos = atomicAdd(&cursor[d], 1);
        ssrc[pos] = src[e];
    }
}

// ================= load-balanced gather + fused epilogue (MLP-4) =================
#define GATHER_BLOCKS 512
__global__ void gather_kernel(const float* __restrict__ M,
                              const int* __restrict__ rowptr,
                              const int* __restrict__ deg,
                              const int* __restrict__ ssrc,
                              const float* __restrict__ norm,
                              const float* __restrict__ b,
                              float* __restrict__ out) {
    const int gw = blockIdx.x * 8 + (threadIdx.x >> 5);
    const int lane = threadIdx.x & 31;
    const int nwarps = GATHER_BLOCKS * 8;
    const float4 bb = __ldg(reinterpret_cast<const float4*>(b) + lane);

    for (int node = gw; node < N_NODES; node += nwarps) {
        const int start = __ldg(rowptr + node);
        const int d = __ldg(deg + node);
        float4 acc = make_float4(0.f, 0.f, 0.f, 0.f);
        int j = 0;
        for (; j + 4 <= d; j += 4) {
            int s0 = __ldg(ssrc + start + j + 0);
            int s1 = __ldg(ssrc + start + j + 1);
            int s2 = __ldg(ssrc + start + j + 2);
            int s3 = __ldg(ssrc + start + j + 3);
            float4 v0 = __ldg(reinterpret_cast<const float4*>(M + (size_t)s0 * HD) + lane);
            float4 v1 = __ldg(reinterpret_cast<const float4*>(M + (size_t)s1 * HD) + lane);
            float4 v2 = __ldg(reinterpret_cast<const float4*>(M + (size_t)s2 * HD) + lane);
            float4 v3 = __ldg(reinterpret_cast<const float4*>(M + (size_t)s3 * HD) + lane);
            acc.x += v0.x + v1.x + v2.x + v3.x;
            acc.y += v0.y + v1.y + v2.y + v3.y;
            acc.z += v0.z + v1.z + v2.z + v3.z;
            acc.w += v0.w + v1.w + v2.w + v3.w;
        }
        for (; j < d; ++j) {
            int s = __ldg(ssrc + start + j);
            float4 v = __ldg(reinterpret_cast<const float4*>(M + (size_t)s * HD) + lane);
            acc.x += v.x; acc.y += v.y; acc.z += v.z; acc.w += v.w;
        }
        const float sc = __ldg(norm + node);
        float4 n;
        n.x = leaky(acc.x * sc + bb.x);
        n.y = leaky(acc.y * sc + bb.y);
        n.z = leaky(acc.z * sc + bb.z);
        n.w = leaky(acc.w * sc + bb.w);
        reinterpret_cast<float4*>(out + (size_t)node * HD)[lane] = n;
    }
}

extern "C" void kernel_launch(void* const* d_in, const int* in_sizes, int n_in,
                              void* d_out, int out_size) {
    const int*   node_id = (const int*)d_in[0];
    const int*   src     = (const int*)d_in[1];
    const int*   dst     = (const int*)d_in[2];
    const float* norm    = (const float*)d_in[3];
    const float* embed   = (const float*)d_in[4];
    const float* W1      = (const float*)d_in[5];
    const float* b1      = (const float*)d_in[6];
    const float* W2      = (const float*)d_in[7];
    const float* b2      = (const float*)d_in[8];
    float* out = (float*)d_out;

    void *pM, *pH, *pDeg, *pRow, *pCur, *pSS, *pPart, *p1h, *p1l, *p2h, *p2l;
    cudaGetSymbolAddress(&pM, g_M);
    cudaGetSymbolAddress(&pH, g_H);
    cudaGetSymbolAddress(&pDeg, g_deg);
    cudaGetSymbolAddress(&pRow, g_rowptr);
    cudaGetSymbolAddress(&pCur, g_cursor);
    cudaGetSymbolAddress(&pSS, g_ssrc);
    cudaGetSymbolAddress(&pPart, g_partials);
    cudaGetSymbolAddress(&p1h, g_W1hi);
    cudaGetSymbolAddress(&p1l, g_W1lo);
    cudaGetSymbolAddress(&p2h, g_W2hi);
    cudaGetSymbolAddress(&p2l, g_W2lo);
    float* M = (float*)pM;
    float* H = (float*)pH;
    int *deg = (int*)pDeg, *rowptr = (int*)pRow, *cursor = (int*)pCur;
    int *ssrc = (int*)pSS, *partials = (int*)pPart;
    __nv_bfloat16 *w1hi = (__nv_bfloat16*)p1h, *w1lo = (__nv_bfloat16*)p1l;
    __nv_bfloat16 *w2hi = (__nv_bfloat16*)p2h, *w2lo = (__nv_bfloat16*)p2l;

    cudaFuncSetAttribute(hmma_gemm_kernel,
                         cudaFuncAttributeMaxDynamicSharedMemorySize, SM_TOTAL);

    const int edge_grid = (N_EDGES + 255) / 256;
    const int node_grid = (N_NODES + 255) / 256;
    const int wt_grid   = (2 * HD * HD + 255) / 256;

    // Launch order keeps the GEMM as the 4th non-memset kernel (ncu window).
    cudaMemsetAsync(deg, 0, N_NODES * sizeof(int));
    hist_kernel<<<edge_grid, 256>>>(dst, deg);
    scan_block_kernel<<<NBLK, 256>>>(deg, rowptr, partials);
    prep_wt_kernel<<<wt_grid, 256>>>(W1, W2, w1hi, w1lo, w2hi, w2lo);

    // ---- Layer 1 GEMM (embedding gather fused) ----
    hmma_gemm_kernel<<<GEMM_CTAS, 256, SM_TOTAL>>>(embed, node_id, w1hi, w1lo, norm, M);

    // CSR back-half:
    scan_partials_kernel<<<1, 128>>>(partials);
    scan_add_kernel<<<node_grid, 256>>>(rowptr, partials, cursor);
    permute_kernel<<<edge_grid, 256>>>(src, dst, cursor, ssrc);

    gather_kernel<<<GATHER_BLOCKS, 256>>>(M, rowptr, deg, ssrc, norm, b1, H);

    // ---- Layer 2 ----
    hmma_gemm_kernel<<<GEMM_CTAS, 256, SM_TOTAL>>>(H, nullptr, w2hi, w2lo, norm, M);
    gather_kernel<<<GATHER_BLOCKS, 256>>>(M, rowptr, deg, ssrc, norm, b2, out);
}

// round 13
// speedup vs baseline: 1.1143x; 1.0334x over previous
#include <cuda_runtime.h>
#include <cuda_bf16.h>
#include <cstdint>
#include <cstddef>

#define N_NODES 100000
#define N_EDGES 600000
#define HD 128
#define TILE_M 64
#define GTILES ((N_NODES + TILE_M - 1) / TILE_M)   // 1563
#define GEMM_CTAS 296
#define SCAN_CHUNK 1024
#define NBLK ((N_NODES + SCAN_CHUNK - 1) / SCAN_CHUNK)   // 98

// ---- scratch (allocation-free) ----
__device__ float g_M[(size_t)N_NODES * HD];
__device__ float g_H[(size_t)N_NODES * HD];
__device__ int   g_deg[N_NODES];
__device__ int   g_rowptr[N_NODES];
__device__ int   g_cursor[N_NODES];
__device__ int   g_ssrc[N_EDGES];
__device__ int   g_agg[NBLK];
__device__ int   g_flag[NBLK];
__device__ unsigned g_ctr[2];
__device__ __nv_bfloat16 g_W1hi[HD * HD];
__device__ __nv_bfloat16 g_W1lo[HD * HD];
__device__ __nv_bfloat16 g_W2hi[HD * HD];
__device__ __nv_bfloat16 g_W2lo[HD * HD];

__device__ __forceinline__ float leaky(float x) { return x > 0.f ? x : 0.2f * x; }

__device__ __forceinline__ uint32_t smem_u32(const void* p) {
    uint32_t a;
    asm("{ .reg .u64 t; cvta.to.shared.u64 t, %1; cvt.u32.u64 %0, t; }" : "=r"(a) : "l"(p));
    return a;
}
// pack two f32 -> bf16x2 (round-to-nearest), first arg in LOW half
__device__ __forceinline__ uint32_t cvt_bf2(float lo_half, float hi_half) {
    uint32_t r;
    asm("cvt.rn.bf16x2.f32 %0, %1, %2;" : "=r"(r) : "f"(hi_half), "f"(lo_half));
    return r;
}
// D += A * B  (m16n8k16 bf16->f32) — plain sm_80 PTX
__device__ __forceinline__ void mma16816(float* d, const uint32_t* a, uint32_t b0, uint32_t b1) {
    asm volatile(
        "mma.sync.aligned.m16n8k16.row.col.f32.bf16.bf16.f32 "
        "{%0,%1,%2,%3}, {%4,%5,%6,%7}, {%8,%9}, {%0,%1,%2,%3};"
        : "+f"(d[0]), "+f"(d[1]), "+f"(d[2]), "+f"(d[3])
        : "r"(a[0]), "r"(a[1]), "r"(a[2]), "r"(a[3]), "r"(b0), "r"(b1));
}
__device__ __forceinline__ void ldsm4(uint32_t* r, uint32_t addr) {
    asm volatile("ldmatrix.sync.aligned.m8n8.x4.shared.b16 {%0,%1,%2,%3}, [%4];"
                 : "=r"(r[0]), "=r"(r[1]), "=r"(r[2]), "=r"(r[3]) : "r"(addr));
}

// ================= W^T hi/lo prep (both layers, one launch) =================
__global__ void prep_wt_kernel(const float* __restrict__ W1,
                               const float* __restrict__ W2,
                               __nv_bfloat16* __restrict__ w1hi,
                               __nv_bfloat16* __restrict__ w1lo,
                               __nv_bfloat16* __restrict__ w2hi,
                               __nv_bfloat16* __restrict__ w2lo) {
    int gid = blockIdx.x * 256 + threadIdx.x;
    int which = gid >= HD * HD;
    int idx = gid - which * HD * HD;
    if (idx >= HD * HD) return;
    const float* W = which ? W2 : W1;
    __nv_bfloat16* whi = which ? w2hi : w1hi;
    __nv_bfloat16* wlo = which ? w2lo : w1lo;
    int n = idx >> 7, k = idx & 127;
    float x = W[k * HD + n];
    __nv_bfloat16 h = __float2bfloat16_rn(x);
    float r = x - __bfloat162float(h);
    whi[idx] = h;
    wlo[idx] = __float2bfloat16_rn(r);
}

// ================= persistent HMMA GEMM, 2 CTAs/SM, dynamic tile scheduler ==
// out[row,:] = (X[gather(row),:] @ W) * norm[row], split-bf16 3-product.
// SMEM per CTA: Bhi 32K | Blo 32K | Ahi 16K | Alo 16K = 96KB (+8B static)
#define SMB_BHI 0
#define SMB_BLO 32768
#define SMB_AHI 65536
#define SMB_ALO 81920
#define SM_TOTAL 98304

__global__ __launch_bounds__(256, 2)
void hmma_gemm_kernel(const float* __restrict__ X,
                      const int* __restrict__ idx,    // nullable
                      const __nv_bfloat16* __restrict__ wt_hi,
                      const __nv_bfloat16* __restrict__ wt_lo,
                      const float* __restrict__ norm,
                      unsigned* __restrict__ ctr,
                      float* __restrict__ out) {
    extern __shared__ char smem[];
    __shared__ int s_next[2];
    const uint32_t sb = smem_u32(smem);
    const int t = threadIdx.x;
    const int lane = t & 31, wid = t >> 5;

    // ---- load B hi/lo once (coalesced: half-warp per row) ----
    {
        #pragma unroll
        for (int p = 0; p < 8; ++p) {
            const int r = wid * 16 + p * 2 + (lane >> 4);   // 0..127
            const int u = lane & 15;                        // uint4 chunk 0..15
            const uint32_t q = (uint32_t)u ^ (uint32_t)(r & 7);
            *reinterpret_cast<uint4*>(smem + SMB_BHI + r * 256 + q * 16) =
                __ldg(reinterpret_cast<const uint4*>(wt_hi + r * HD) + u);
            *reinterpret_cast<uint4*>(smem + SMB_BLO + r * 256 + q * 16) =
                __ldg(reinterpret_cast<const uint4*>(wt_lo + r * HD) + u);
        }
    }

    // ---- warp tiling: 8 warps = 2 row-groups x 4 col-groups; warp tile 32x32 ----
    const int wr = wid >> 2, wc = wid & 3;
    const int g = lane >> 2, tq = lane & 3;

    // ldmatrix lane mapping (validated rounds 7-11)
    const int sub = lane >> 3, subrow = lane & 7;
    const int cs = sub >> 1;
    const int s8 = (sub & 1) * 8;
    const int rB0 = wc * 32 + s8 + subrow;
    const int rB1 = rB0 + 16;
    const int rA0 = wr * 32 + s8 + subrow;
    const int rA1 = rA0 + 16;
    const uint32_t baB0 = rB0 * 256, r7B0 = rB0 & 7;
    const uint32_t baB1 = rB1 * 256, r7B1 = rB1 & 7;
    const uint32_t baA0 = rA0 * 256, r7A0 = rA0 & 7;
    const uint32_t baA1 = rA1 * 256, r7A1 = rA1 & 7;
    const uint32_t bHI = sb + SMB_BHI, bLO = sb + SMB_BLO;
    const uint32_t aHI = sb + SMB_AHI, aLO = sb + SMB_ALO;

    // A staging coords (high-MLP layout: 4 threads/row, 8 float4 each)
    const int sr_ = t >> 2;            // local row 0..63
    const int sq_ = t & 3;

    float4 pf[8];                      // register prefetch buffer

    auto load_tile = [&](int tile) {
        const int row = tile * TILE_M + sr_;
        if (row < N_NODES) {
            const int srow = idx ? __ldg(idx + row) : row;
            const float4* gsrc = reinterpret_cast<const float4*>(X + (size_t)srow * HD);
            #pragma unroll
            for (int j = 0; j < 8; ++j) pf[j] = __ldg(gsrc + sq_ * 8 + j);
        } else {
            #pragma unroll
            for (int j = 0; j < 8; ++j) pf[j] = make_float4(0.f, 0.f, 0.f, 0.f);
        }
    };
    auto sts_tile = [&]() {
        char* DH = smem + SMB_AHI + sr_ * 256;
        char* DL = smem + SMB_ALO + sr_ * 256;
        #pragma unroll
        for (int j = 0; j < 8; ++j) {
            const int c4 = sq_ * 8 + j;
            float4 v = pf[j];
            uint32_t h0 = __byte_perm(__float_as_uint(v.x), __float_as_uint(v.y), 0x7632);
            uint32_t h1 = __byte_perm(__float_as_uint(v.z), __float_as_uint(v.w), 0x7632);
            uint32_t l0 = cvt_bf2(v.x - __uint_as_float(h0 << 16),
                                  v.y - __uint_as_float(h0 & 0xFFFF0000u));
            uint32_t l1 = cvt_bf2(v.z - __uint_as_float(h1 << 16),
                                  v.w - __uint_as_float(h1 & 0xFFFF0000u));
            uint32_t chunk = ((uint32_t)(c4 >> 1)) ^ (uint32_t)(sr_ & 7);
            uint32_t off = chunk * 16 + ((uint32_t)(2 * c4) & 3) * 4;
            *reinterpret_cast<uint2*>(DH + off) = make_uint2(h0, h1);
            *reinterpret_cast<uint2*>(DL + off) = make_uint2(l0, l1);
        }
    };

    // ---- dynamic scheduler prologue ----
    if (t == 0) s_next[0] = (int)atomicAdd(ctr, 1u);
    __syncthreads();
    int cur = s_next[0];
    if (cur >= GTILES) return;     // (grid <= GTILES, shouldn't happen)
    load_tile(cur);

    for (int it = 0; ; ++it) {
        // fetch next tile id into the OTHER slot (ping-pong; race-free across iters)
        if (t == 0) s_next[(it + 1) & 1] = (int)atomicAdd(ctr, 1u);
        sts_tile();                // convert + store prefetched tile `cur`
        __syncthreads();           // A visible + s_next visible (+ B on first iter)
        const int nxt = s_next[(it + 1) & 1];
        if (nxt < GTILES) load_tile(nxt);   // LDGs in flight during compute

        const int row0 = cur * TILE_M;

        float acc[2][4][4];
        #pragma unroll
        for (int mt = 0; mt < 2; ++mt)
            #pragma unroll
            for (int nt = 0; nt < 4; ++nt)
                #pragma unroll
                for (int c = 0; c < 4; ++c) acc[mt][nt][c] = 0.f;

        #pragma unroll
        for (int s = 0; s < 8; ++s) {
            const uint32_t ck = (uint32_t)(2 * s + cs);
            const uint32_t oA0 = baA0 + ((ck ^ r7A0) << 4);
            const uint32_t oA1 = baA1 + ((ck ^ r7A1) << 4);
            const uint32_t oB0 = baB0 + ((ck ^ r7B0) << 4);
            const uint32_t oB1 = baB1 + ((ck ^ r7B1) << 4);

            uint32_t ah0[4], al0[4], ah1[4], al1[4];
            uint32_t bh0[4], bl0[4], bh1[4], bl1[4];
            ldsm4(ah0, aHI + oA0); ldsm4(al0, aLO + oA0);
            ldsm4(ah1, aHI + oA1); ldsm4(al1, aLO + oA1);
            ldsm4(bh0, bHI + oB0); ldsm4(bl0, bLO + oB0);
            ldsm4(bh1, bHI + oB1); ldsm4(bl1, bLO + oB1);

            #pragma unroll
            for (int mt = 0; mt < 2; ++mt) {
                const uint32_t* ah = mt ? ah1 : ah0;
                const uint32_t* al = mt ? al1 : al0;
                mma16816(acc[mt][0], ah, bh0[0], bh0[2]);
                mma16816(acc[mt][0], ah, bl0[0], bl0[2]);
                mma16816(acc[mt][0], al, bh0[0], bh0[2]);
                mma16816(acc[mt][1], ah, bh0[1], bh0[3]);
                mma16816(acc[mt][1], ah, bl0[1], bl0[3]);
                mma16816(acc[mt][1], al, bh0[1], bh0[3]);
                mma16816(acc[mt][2], ah, bh1[0], bh1[2]);
                mma16816(acc[mt][2], ah, bl1[0], bl1[2]);
                mma16816(acc[mt][2], al, bh1[0], bh1[2]);
                mma16816(acc[mt][3], ah, bh1[1], bh1[3]);
                mma16816(acc[mt][3], ah, bl1[1], bl1[3]);
                mma16816(acc[mt][3], al, bh1[1], bh1[3]);
            }
        }

        // ---- epilogue: * norm, store f32 ----
        #pragma unroll
        for (int mt = 0; mt < 2; ++mt) {
            const int rA = row0 + wr * 32 + mt * 16 + g;
            const int rB = rA + 8;
            const bool okA = rA < N_NODES, okB = rB < N_NODES;
            const float sA = okA ? __ldg(norm + rA) : 0.f;
            const float sB = okB ? __ldg(norm + rB) : 0.f;
            #pragma unroll
            for (int nt = 0; nt < 4; ++nt) {
                const int col = wc * 32 + nt * 8 + tq * 2;
                if (okA) {
                    float2 v = make_float2(acc[mt][nt][0] * sA, acc[mt][nt][1] * sA);
                    *reinterpret_cast<float2*>(out + (size_t)rA * HD + col) = v;
                }
                if (okB) {
                    float2 v = make_float2(acc[mt][nt][2] * sB, acc[mt][nt][3] * sB);
                    *reinterpret_cast<float2*>(out + (size_t)rB * HD + col) = v;
                }
            }
        }
        __syncthreads();   // readers done before next STS overwrites A
        if (nxt >= GTILES) break;
        cur = nxt;
    }
}

// ================= CSR build =================

// hist + zero the scan flags and the GEMM tile counters (no extra launches)
__global__ void hist_kernel(const int* __restrict__ dst, int* __restrict__ deg,
                            int* __restrict__ flag, unsigned* __restrict__ ctr) {
    int e = blockIdx.x * 256 + threadIdx.x;
    if (blockIdx.x == 0) {
        if (threadIdx.x < NBLK) flag[threadIdx.x] = 0;
        if (threadIdx.x < 2) ctr[threadIdx.x] = 0u;
    }
    if (e < N_EDGES) atomicAdd(&deg[dst[e]], 1);
}

// single-pass scan: all NBLK=98 blocks co-resident -> direct aggregate lookback
__global__ void scan_all_kernel(const int* __restrict__ deg,
                                int* __restrict__ rowptr,
                                int* __restrict__ cursor,
                                int* __restrict__ agg,
                                int* __restrict__ flag) {
    __shared__ int wsum[8];
    __shared__ int rsum[8];
    __shared__ int s_off;
    const int b = blockIdx.x;
    const int t = threadIdx.x;          // 256
    const int base = b * SCAN_CHUNK + t * 4;
    int v[4];
    #pragma unroll
    for (int j = 0; j < 4; ++j) {
        int i = base + j;
        v[j] = (i < N_NODES) ? deg[i] : 0;
    }
    int s = v[0] + v[1] + v[2] + v[3];
    const int lane = t & 31, wid = t >> 5;
    int x = s;
    #pragma unroll
    for (int o = 1; o < 32; o <<= 1) {
        int y = __shfl_up_sync(~0u, x, o);
        if (lane >= o) x += y;
    }
    if (lane == 31) wsum[wid] = x;
    __syncthreads();
    if (wid == 0) {
        int ws = (lane < 8) ? wsum[lane] : 0;
        #pragma unroll
        for (int o = 1; o < 8; o <<= 1) {
            int y = __shfl_up_sync(~0u, ws, o);
            if (lane >= o) ws += y;
        }
        if (lane < 8) wsum[lane] = ws;   // inclusive warp totals
    }
    __syncthreads();
    int run = (x - s) + (wid > 0 ? wsum[wid - 1] : 0);  // intra-block exclusive prefix

    // publish block aggregate
    if (t == 0) {
        agg[b] = wsum[7];
        __threadfence();
        atomicExch(&flag[b], 1);
    }
    // lookback: thread t polls predecessor t (t < b); all blocks co-resident
    int contrib = 0;
    if (t < b) {
        while (atomicAdd(&flag[t], 0) == 0) {}
        contrib = __ldg(agg + t);
    }
    #pragma unroll
    for (int o = 16; o > 0; o >>= 1) contrib += __shfl_down_sync(~0u, contrib, o);
    if (lane == 0) rsum[wid] = contrib;
    __syncthreads();
    if (t == 0) {
        int a = 0;
        #pragma unroll
        for (int w = 0; w < 8; ++w) a += rsum[w];
        s_off = a;
    }
    __syncthreads();
    run += s_off;
    #pragma unroll
    for (int j = 0; j < 4; ++j) {
        int i = base + j;
        if (i < N_NODES) { rowptr[i] = run; cursor[i] = run; }
        run += v[j];
    }
}

__global__ void permute_kernel(const int* __restrict__ src,
                               const int* __restrict__ dst,
                               int* __restrict__ cursor,
                               int* __restrict__ ssrc) {
    int e = blockIdx.x * 256 + threadIdx.x;
    if (e < N_EDGES) {
        int d = dst[e];
        int pos = atomicAdd(&cursor[d], 1);
        ssrc[pos] = src[e];
    }
}

// ================= load-balanced gather + fused epilogue (MLP-4) =================
#define GATHER_BLOCKS 512
__global__ void gather_kernel(const float* __restrict__ M,
                              const int* __restrict__ rowptr,
                              const int* __restrict__ deg,
                              const int* __restrict__ ssrc,
                              const float* __restrict__ norm,
                              const float* __restrict__ b,
                              float* __restrict__ out) {
    const int gw = blockIdx.x * 8 + (threadIdx.x >> 5);
    const int lane = threadIdx.x & 31;
    const int nwarps = GATHER_BLOCKS * 8;
    const float4 bb = __ldg(reinterpret_cast<const float4*>(b) + lane);

    for (int node = gw; node < N_NODES; node += nwarps) {
        const int start = __ldg(rowptr + node);
        const int d = __ldg(deg + node);
        float4 acc = make_float4(0.f, 0.f, 0.f, 0.f);
        int j = 0;
        for (; j + 4 <= d; j += 4) {
            int s0 = __ldg(ssrc + start + j + 0);
            int s1 = __ldg(ssrc + start + j + 1);
            int s2 = __ldg(ssrc + start + j + 2);
            int s3 = __ldg(ssrc + start + j + 3);
            float4 v0 = __ldg(reinterpret_cast<const float4*>(M + (size_t)s0 * HD) + lane);
            float4 v1 = __ldg(reinterpret_cast<const float4*>(M + (size_t)s1 * HD) + lane);
            float4 v2 = __ldg(reinterpret_cast<const float4*>(M + (size_t)s2 * HD) + lane);
            float4 v3 = __ldg(reinterpret_cast<const float4*>(M + (size_t)s3 * HD) + lane);
            acc.x += v0.x + v1.x + v2.x + v3.x;
            acc.y += v0.y + v1.y + v2.y + v3.y;
            acc.z += v0.z + v1.z + v2.z + v3.z;
            acc.w += v0.w + v1.w + v2.w + v3.w;
        }
        for (; j < d; ++j) {
            int s = __ldg(ssrc + start + j);
            float4 v = __ldg(reinterpret_cast<const float4*>(M + (size_t)s * HD) + lane);
            acc.x += v.x; acc.y += v.y; acc.z += v.z; acc.w += v.w;
        }
        const float sc = __ldg(norm + node);
        float4 n;
        n.x = leaky(acc.x * sc + bb.x);
        n.y = leaky(acc.y * sc + bb.y);
        n.z = leaky(acc.z * sc + bb.z);
        n.w = leaky(acc.w * sc + bb.w);
        reinterpret_cast<float4*>(out + (size_t)node * HD)[lane] = n;
    }
}

extern "C" void kernel_launch(void* const* d_in, const int* in_sizes, int n_in,
                              void* d_out, int out_size) {
    const int*   node_id = (const int*)d_in[0];
    const int*   src     = (const int*)d_in[1];
    const int*   dst     = (const int*)d_in[2];
    const float* norm    = (const float*)d_in[3];
    const float* embed   = (const float*)d_in[4];
    const float* W1      = (const float*)d_in[5];
    const float* b1      = (const float*)d_in[6];
    const float* W2      = (const float*)d_in[7];
    const float* b2      = (const float*)d_in[8];
    float* out = (float*)d_out;

    void *pM, *pH, *pDeg, *pRow, *pCur, *pSS, *pAgg, *pFlag, *pCtr;
    void *p1h, *p1l, *p2h, *p2l;
    cudaGetSymbolAddress(&pM, g_M);
    cudaGetSymbolAddress(&pH, g_H);
    cudaGetSymbolAddress(&pDeg, g_deg);
    cudaGetSymbolAddress(&pRow, g_rowptr);
    cudaGetSymbolAddress(&pCur, g_cursor);
    cudaGetSymbolAddress(&pSS, g_ssrc);
    cudaGetSymbolAddress(&pAgg, g_agg);
    cudaGetSymbolAddress(&pFlag, g_flag);
    cudaGetSymbolAddress(&pCtr, g_ctr);
    cudaGetSymbolAddress(&p1h, g_W1hi);
    cudaGetSymbolAddress(&p1l, g_W1lo);
    cudaGetSymbolAddress(&p2h, g_W2hi);
    cudaGetSymbolAddress(&p2l, g_W2lo);
    float* M = (float*)pM;
    float* H = (float*)pH;
    int *deg = (int*)pDeg, *rowptr = (int*)pRow, *cursor = (int*)pCur;
    int *ssrc = (int*)pSS, *agg = (int*)pAgg, *flag = (int*)pFlag;
    unsigned* ctr = (unsigned*)pCtr;
    __nv_bfloat16 *w1hi = (__nv_bfloat16*)p1h, *w1lo = (__nv_bfloat16*)p1l;
    __nv_bfloat16 *w2hi = (__nv_bfloat16*)p2h, *w2lo = (__nv_bfloat16*)p2l;

    cudaFuncSetAttribute(hmma_gemm_kernel,
                         cudaFuncAttributeMaxDynamicSharedMemorySize, SM_TOTAL);

    const int edge_grid = (N_EDGES + 255) / 256;
    const int wt_grid   = (2 * HD * HD + 255) / 256;

    cudaMemsetAsync(deg, 0, N_NODES * sizeof(int));
    hist_kernel<<<edge_grid, 256>>>(dst, deg, flag, ctr);
    scan_all_kernel<<<NBLK, 256>>>(deg, rowptr, cursor, agg, flag);
    prep_wt_kernel<<<wt_grid, 256>>>(W1, W2, w1hi, w1lo, w2hi, w2lo);

    // ---- Layer 1 GEMM (embedding gather fused) ----
    hmma_gemm_kernel<<<GEMM_CTAS, 256, SM_TOTAL>>>(embed, node_id, w1hi, w1lo, norm, ctr + 0, M);

    permute_kernel<<<edge_grid, 256>>>(src, dst, cursor, ssrc);
    gather_kernel<<<GATHER_BLOCKS, 256>>>(M, rowptr, deg, ssrc, norm, b1, H);

    // ---- Layer 2 ----
    hmma_gemm_kernel<<<GEMM_CTAS, 256, SM_TOTAL>>>(H, nullptr, w2hi, w2lo, norm, ctr + 1, M);
    gather_kernel<<<GATHER_BLOCKS, 256>>>(M, rowptr, deg, ssrc, norm, b2, out);
}

// round 14
// speedup vs baseline: 1.1852x; 1.0636x over previous
#include <cuda_runtime.h>
#include <cuda_bf16.h>
#include <cstdint>
#include <cstddef>

#define N_NODES 100000
#define N_EDGES 600000
#define HD 128
#define TILE_M 64
#define GTILES ((N_NODES + TILE_M - 1) / TILE_M)   // 1563
#define GEMM_CTAS 296
#define SCAN_CHUNK 1024
#define NBLK ((N_NODES + SCAN_CHUNK - 1) / SCAN_CHUNK)   // 98
#define EDGE_GRID ((N_EDGES + 255) / 256)                // 2344
#define WT_GRID ((2 * HD * HD + 255) / 256)              // 128

// ---- scratch (allocation-free) ----
__device__ float g_M[(size_t)N_NODES * HD];
__device__ float g_H[(size_t)N_NODES * HD];
__device__ int   g_deg[N_NODES];
__device__ int   g_rowptr[N_NODES];
__device__ int   g_cursor[N_NODES];
__device__ int   g_ssrc[N_EDGES];
__device__ int   g_agg[NBLK];
__device__ int   g_flag[NBLK];
__device__ unsigned g_ctr[2];
__device__ __nv_bfloat16 g_W1hi[HD * HD];
__device__ __nv_bfloat16 g_W1lo[HD * HD];
__device__ __nv_bfloat16 g_W2hi[HD * HD];
__device__ __nv_bfloat16 g_W2lo[HD * HD];

__device__ __forceinline__ float leaky(float x) { return x > 0.f ? x : 0.2f * x; }

__device__ __forceinline__ uint32_t smem_u32(const void* p) {
    uint32_t a;
    asm("{ .reg .u64 t; cvta.to.shared.u64 t, %1; cvt.u32.u64 %0, t; }" : "=r"(a) : "l"(p));
    return a;
}
// pack two f32 -> bf16x2 (round-to-nearest), first arg in LOW half
__device__ __forceinline__ uint32_t cvt_bf2(float lo_half, float hi_half) {
    uint32_t r;
    asm("cvt.rn.bf16x2.f32 %0, %1, %2;" : "=r"(r) : "f"(hi_half), "f"(lo_half));
    return r;
}
// D += A * B  (m16n8k16 bf16->f32) — plain sm_80 PTX
__device__ __forceinline__ void mma16816(float* d, const uint32_t* a, uint32_t b0, uint32_t b1) {
    asm volatile(
        "mma.sync.aligned.m16n8k16.row.col.f32.bf16.bf16.f32 "
        "{%0,%1,%2,%3}, {%4,%5,%6,%7}, {%8,%9}, {%0,%1,%2,%3};"
        : "+f"(d[0]), "+f"(d[1]), "+f"(d[2]), "+f"(d[3])
        : "r"(a[0]), "r"(a[1]), "r"(a[2]), "r"(a[3]), "r"(b0), "r"(b1));
}
__device__ __forceinline__ void ldsm4(uint32_t* r, uint32_t addr) {
    asm volatile("ldmatrix.sync.aligned.m8n8.x4.shared.b16 {%0,%1,%2,%3}, [%4];"
                 : "=r"(r[0]), "=r"(r[1]), "=r"(r[2]), "=r"(r[3]) : "r"(addr));
}

// ================= hist + flag/ctr zero + W^T hi/lo prep (one launch) =======
__global__ void hist_prep_kernel(const int* __restrict__ dst, int* __restrict__ deg,
                                 int* __restrict__ flag, unsigned* __restrict__ ctr,
                                 const float* __restrict__ W1,
                                 const float* __restrict__ W2,
                                 __nv_bfloat16* __restrict__ w1hi,
                                 __nv_bfloat16* __restrict__ w1lo,
                                 __nv_bfloat16* __restrict__ w2hi,
                                 __nv_bfloat16* __restrict__ w2lo) {
    if (blockIdx.x < EDGE_GRID) {
        int e = blockIdx.x * 256 + threadIdx.x;
        if (blockIdx.x == 0) {
            if (threadIdx.x < NBLK) flag[threadIdx.x] = 0;
            if (threadIdx.x < 2) ctr[threadIdx.x] = 0u;
        }
        if (e < N_EDGES) atomicAdd(&deg[dst[e]], 1);
    } else {
        int gid = (blockIdx.x - EDGE_GRID) * 256 + threadIdx.x;
        int which = gid >= HD * HD;
        int idx = gid - which * HD * HD;
        if (idx >= HD * HD) return;
        const float* W = which ? W2 : W1;
        __nv_bfloat16* whi = which ? w2hi : w1hi;
        __nv_bfloat16* wlo = which ? w2lo : w1lo;
        int n = idx >> 7, k = idx & 127;
        float x = W[k * HD + n];
        __nv_bfloat16 h = __float2bfloat16_rn(x);
        float r = x - __bfloat162float(h);
        whi[idx] = h;
        wlo[idx] = __float2bfloat16_rn(r);
    }
}

// ================= persistent HMMA GEMM, 2 CTAs/SM, dynamic tile scheduler ==
// out[row,:] = (X[gather(row),:] @ W) * norm[row], split-bf16 3-product.
// SMEM per CTA: Bhi 32K | Blo 32K | Ahi 16K | Alo 16K = 96KB (+8B static)
#define SMB_BHI 0
#define SMB_BLO 32768
#define SMB_AHI 65536
#define SMB_ALO 81920
#define SM_TOTAL 98304

__global__ __launch_bounds__(256, 2)
void hmma_gemm_kernel(const float* __restrict__ X,
                      const int* __restrict__ idx,    // nullable
                      const __nv_bfloat16* __restrict__ wt_hi,
                      const __nv_bfloat16* __restrict__ wt_lo,
                      const float* __restrict__ norm,
                      unsigned* __restrict__ ctr,
                      float* __restrict__ out) {
    extern __shared__ char smem[];
    __shared__ int s_next[2];
    const uint32_t sb = smem_u32(smem);
    const int t = threadIdx.x;
    const int lane = t & 31, wid = t >> 5;

    // ---- load B hi/lo once (coalesced: half-warp per row) ----
    {
        #pragma unroll
        for (int p = 0; p < 8; ++p) {
            const int r = wid * 16 + p * 2 + (lane >> 4);   // 0..127
            const int u = lane & 15;                        // uint4 chunk 0..15
            const uint32_t q = (uint32_t)u ^ (uint32_t)(r & 7);
            *reinterpret_cast<uint4*>(smem + SMB_BHI + r * 256 + q * 16) =
                __ldg(reinterpret_cast<const uint4*>(wt_hi + r * HD) + u);
            *reinterpret_cast<uint4*>(smem + SMB_BLO + r * 256 + q * 16) =
                __ldg(reinterpret_cast<const uint4*>(wt_lo + r * HD) + u);
        }
    }

    // ---- warp tiling: 8 warps = 2 row-groups x 4 col-groups; warp tile 32x32 ----
    const int wr = wid >> 2, wc = wid & 3;
    const int g = lane >> 2, tq = lane & 3;

    // ldmatrix lane mapping (validated rounds 7-13)
    const int sub = lane >> 3, subrow = lane & 7;
    const int cs = sub >> 1;
    const int s8 = (sub & 1) * 8;
    const int rB0 = wc * 32 + s8 + subrow;
    const int rB1 = rB0 + 16;
    const int rA0 = wr * 32 + s8 + subrow;
    const int rA1 = rA0 + 16;
    const uint32_t baB0 = rB0 * 256, r7B0 = rB0 & 7;
    const uint32_t baB1 = rB1 * 256, r7B1 = rB1 & 7;
    const uint32_t baA0 = rA0 * 256, r7A0 = rA0 & 7;
    const uint32_t baA1 = rA1 * 256, r7A1 = rA1 & 7;
    const uint32_t bHI = sb + SMB_BHI, bLO = sb + SMB_BLO;
    const uint32_t aHI = sb + SMB_AHI, aLO = sb + SMB_ALO;

    // A staging coords (high-MLP layout: 4 threads/row, 8 float4 each)
    const int sr_ = t >> 2;            // local row 0..63
    const int sq_ = t & 3;

    float4 pf[8];                      // register prefetch buffer

    auto load_tile = [&](int tile) {
        const int row = tile * TILE_M + sr_;
        if (row < N_NODES) {
            const int srow = idx ? __ldg(idx + row) : row;
            const float4* gsrc = reinterpret_cast<const float4*>(X + (size_t)srow * HD);
            #pragma unroll
            for (int j = 0; j < 8; ++j) pf[j] = __ldg(gsrc + sq_ * 8 + j);
        } else {
            #pragma unroll
            for (int j = 0; j < 8; ++j) pf[j] = make_float4(0.f, 0.f, 0.f, 0.f);
        }
    };
    auto sts_tile = [&]() {
        char* DH = smem + SMB_AHI + sr_ * 256;
        char* DL = smem + SMB_ALO + sr_ * 256;
        #pragma unroll
        for (int j = 0; j < 8; ++j) {
            const int c4 = sq_ * 8 + j;
            float4 v = pf[j];
            uint32_t h0 = __byte_perm(__float_as_uint(v.x), __float_as_uint(v.y), 0x7632);
            uint32_t h1 = __byte_perm(__float_as_uint(v.z), __float_as_uint(v.w), 0x7632);
            uint32_t l0 = cvt_bf2(v.x - __uint_as_float(h0 << 16),
                                  v.y - __uint_as_float(h0 & 0xFFFF0000u));
            uint32_t l1 = cvt_bf2(v.z - __uint_as_float(h1 << 16),
                                  v.w - __uint_as_float(h1 & 0xFFFF0000u));
            uint32_t chunk = ((uint32_t)(c4 >> 1)) ^ (uint32_t)(sr_ & 7);
            uint32_t off = chunk * 16 + ((uint32_t)(2 * c4) & 3) * 4;
            *reinterpret_cast<uint2*>(DH + off) = make_uint2(h0, h1);
            *reinterpret_cast<uint2*>(DL + off) = make_uint2(l0, l1);
        }
    };

    // ---- dynamic scheduler prologue ----
    if (t == 0) s_next[0] = (int)atomicAdd(ctr, 1u);
    __syncthreads();
    int cur = s_next[0];
    if (cur >= GTILES) return;
    load_tile(cur);

    for (int it = 0; ; ++it) {
        if (t == 0) s_next[(it + 1) & 1] = (int)atomicAdd(ctr, 1u);
        sts_tile();
        __syncthreads();
        const int nxt = s_next[(it + 1) & 1];
        if (nxt < GTILES) load_tile(nxt);

        const int row0 = cur * TILE_M;

        float acc[2][4][4];
        #pragma unroll
        for (int mt = 0; mt < 2; ++mt)
            #pragma unroll
            for (int nt = 0; nt < 4; ++nt)
                #pragma unroll
                for (int c = 0; c < 4; ++c) acc[mt][nt][c] = 0.f;

        #pragma unroll
        for (int s = 0; s < 8; ++s) {
            const uint32_t ck = (uint32_t)(2 * s + cs);
            const uint32_t oA0 = baA0 + ((ck ^ r7A0) << 4);
            const uint32_t oA1 = baA1 + ((ck ^ r7A1) << 4);
            const uint32_t oB0 = baB0 + ((ck ^ r7B0) << 4);
            const uint32_t oB1 = baB1 + ((ck ^ r7B1) << 4);

            uint32_t ah0[4], al0[4], ah1[4], al1[4];
            uint32_t bh0[4], bl0[4], bh1[4], bl1[4];
            ldsm4(ah0, aHI + oA0); ldsm4(al0, aLO + oA0);
            ldsm4(ah1, aHI + oA1); ldsm4(al1, aLO + oA1);
            ldsm4(bh0, bHI + oB0); ldsm4(bl0, bLO + oB0);
            ldsm4(bh1, bHI + oB1); ldsm4(bl1, bLO + oB1);

            #pragma unroll
            for (int mt = 0; mt < 2; ++mt) {
                const uint32_t* ah = mt ? ah1 : ah0;
                const uint32_t* al = mt ? al1 : al0;
                mma16816(acc[mt][0], ah, bh0[0], bh0[2]);
                mma16816(acc[mt][0], ah, bl0[0], bl0[2]);
                mma16816(acc[mt][0], al, bh0[0], bh0[2]);
                mma16816(acc[mt][1], ah, bh0[1], bh0[3]);
                mma16816(acc[mt][1], ah, bl0[1], bl0[3]);
                mma16816(acc[mt][1], al, bh0[1], bh0[3]);
                mma16816(acc[mt][2], ah, bh1[0], bh1[2]);
                mma16816(acc[mt][2], ah, bl1[0], bl1[2]);
                mma16816(acc[mt][2], al, bh1[0], bh1[2]);
                mma16816(acc[mt][3], ah, bh1[1], bh1[3]);
                mma16816(acc[mt][3], ah, bl1[1], bl1[3]);
                mma16816(acc[mt][3], al, bh1[1], bh1[3]);
            }
        }

        // ---- epilogue: * norm, store f32 ----
        #pragma unroll
        for (int mt = 0; mt < 2; ++mt) {
            const int rA = row0 + wr * 32 + mt * 16 + g;
            const int rB = rA + 8;
            const bool okA = rA < N_NODES, okB = rB < N_NODES;
            const float sA = okA ? __ldg(norm + rA) : 0.f;
            const float sB = okB ? __ldg(norm + rB) : 0.f;
            #pragma unroll
            for (int nt = 0; nt < 4; ++nt) {
                const int col = wc * 32 + nt * 8 + tq * 2;
                if (okA) {
                    float2 v = make_float2(acc[mt][nt][0] * sA, acc[mt][nt][1] * sA);
                    *reinterpret_cast<float2*>(out + (size_t)rA * HD + col) = v;
                }
                if (okB) {
                    float2 v = make_float2(acc[mt][nt][2] * sB, acc[mt][nt][3] * sB);
                    *reinterpret_cast<float2*>(out + (size_t)rB * HD + col) = v;
                }
            }
        }
        __syncthreads();
        if (nxt >= GTILES) break;
        cur = nxt;
    }
}

// single-pass scan: all NBLK=98 blocks co-resident -> direct aggregate lookback
__global__ void scan_all_kernel(const int* __restrict__ deg,
                                int* __restrict__ rowptr,
                                int* __restrict__ cursor,
                                int* __restrict__ agg,
                                int* __restrict__ flag) {
    __shared__ int wsum[8];
    __shared__ int rsum[8];
    __shared__ int s_off;
    const int b = blockIdx.x;
    const int t = threadIdx.x;
    const int base = b * SCAN_CHUNK + t * 4;
    int v[4];
    #pragma unroll
    for (int j = 0; j < 4; ++j) {
        int i = base + j;
        v[j] = (i < N_NODES) ? deg[i] : 0;
    }
    int s = v[0] + v[1] + v[2] + v[3];
    const int lane = t & 31, wid = t >> 5;
    int x = s;
    #pragma unroll
    for (int o = 1; o < 32; o <<= 1) {
        int y = __shfl_up_sync(~0u, x, o);
        if (lane >= o) x += y;
    }
    if (lane == 31) wsum[wid] = x;
    __syncthreads();
    if (wid == 0) {
        int ws = (lane < 8) ? wsum[lane] : 0;
        #pragma unroll
        for (int o = 1; o < 8; o <<= 1) {
            int y = __shfl_up_sync(~0u, ws, o);
            if (lane >= o) ws += y;
        }
        if (lane < 8) wsum[lane] = ws;
    }
    __syncthreads();
    int run = (x - s) + (wid > 0 ? wsum[wid - 1] : 0);

    if (t == 0) {
        agg[b] = wsum[7];
        __threadfence();
        atomicExch(&flag[b], 1);
    }
    int contrib = 0;
    if (t < b) {
        while (atomicAdd(&flag[t], 0) == 0) {}
        contrib = __ldg(agg + t);
    }
    #pragma unroll
    for (int o = 16; o > 0; o >>= 1) contrib += __shfl_down_sync(~0u, contrib, o);
    if (lane == 0) rsum[wid] = contrib;
    __syncthreads();
    if (t == 0) {
        int a = 0;
        #pragma unroll
        for (int w = 0; w < 8; ++w) a += rsum[w];
        s_off = a;
    }
    __syncthreads();
    run += s_off;
    #pragma unroll
    for (int j = 0; j < 4; ++j) {
        int i = base + j;
        if (i < N_NODES) { rowptr[i] = run; cursor[i] = run; }
        run += v[j];
    }
}

__global__ void permute_kernel(const int* __restrict__ src,
                               const int* __restrict__ dst,
                               int* __restrict__ cursor,
                               int* __restrict__ ssrc) {
    int e = blockIdx.x * 256 + threadIdx.x;
    if (e < N_EDGES) {
        int d = dst[e];
        int pos = atomicAdd(&cursor[d], 1);
        ssrc[pos] = src[e];
    }
}

// ================= load-balanced gather + fused epilogue (MLP-4, full occ) ===
#define GATHER_BLOCKS 1184
__global__ void gather_kernel(const float* __restrict__ M,
                              const int* __restrict__ rowptr,
                              const int* __restrict__ deg,
                              const int* __restrict__ ssrc,
                              const float* __restrict__ norm,
                              const float* __restrict__ b,
                              float* __restrict__ out) {
    const int gw = blockIdx.x * 8 + (threadIdx.x >> 5);
    const int lane = threadIdx.x & 31;
    const int nwarps = GATHER_BLOCKS * 8;
    const float4 bb = __ldg(reinterpret_cast<const float4*>(b) + lane);

    for (int node = gw; node < N_NODES; node += nwarps) {
        const int start = __ldg(rowptr + node);
        const int d = __ldg(deg + node);
        float4 acc = make_float4(0.f, 0.f, 0.f, 0.f);
        int j = 0;
        for (; j + 4 <= d; j += 4) {
            int s0 = __ldg(ssrc + start + j + 0);
            int s1 = __ldg(ssrc + start + j + 1);
            int s2 = __ldg(ssrc + start + j + 2);
            int s3 = __ldg(ssrc + start + j + 3);
            float4 v0 = __ldg(reinterpret_cast<const float4*>(M + (size_t)s0 * HD) + lane);
            float4 v1 = __ldg(reinterpret_cast<const float4*>(M + (size_t)s1 * HD) + lane);
            float4 v2 = __ldg(reinterpret_cast<const float4*>(M + (size_t)s2 * HD) + lane);
            float4 v3 = __ldg(reinterpret_cast<const float4*>(M + (size_t)s3 * HD) + lane);
            acc.x += v0.x + v1.x + v2.x + v3.x;
            acc.y += v0.y + v1.y + v2.y + v3.y;
            acc.z += v0.z + v1.z + v2.z + v3.z;
            acc.w += v0.w + v1.w + v2.w + v3.w;
        }
        for (; j < d; ++j) {
            int s = __ldg(ssrc + start + j);
            float4 v = __ldg(reinterpret_cast<const float4*>(M + (size_t)s * HD) + lane);
            acc.x += v.x; acc.y += v.y; acc.z += v.z; acc.w += v.w;
        }
        const float sc = __ldg(norm + node);
        float4 n;
        n.x = leaky(acc.x * sc + bb.x);
        n.y = leaky(acc.y * sc + bb.y);
        n.z = leaky(acc.z * sc + bb.z);
        n.w = leaky(acc.w * sc + bb.w);
        reinterpret_cast<float4*>(out + (size_t)node * HD)[lane] = n;
    }
}

extern "C" void kernel_launch(void* const* d_in, const int* in_sizes, int n_in,
                              void* d_out, int out_size) {
    const int*   node_id = (const int*)d_in[0];
    const int*   src     = (const int*)d_in[1];
    const int*   dst     = (const int*)d_in[2];
    const float* norm    = (const float*)d_in[3];
    const float* embed   = (const float*)d_in[4];
    const float* W1      = (const float*)d_in[5];
    const float* b1      = (const float*)d_in[6];
    const float* W2      = (const float*)d_in[7];
    const float* b2      = (const float*)d_in[8];
    float* out = (float*)d_out;

    void *pM, *pH, *pDeg, *pRow, *pCur, *pSS, *pAgg, *pFlag, *pCtr;
    void *p1h, *p1l, *p2h, *p2l;
    cudaGetSymbolAddress(&pM, g_M);
    cudaGetSymbolAddress(&pH, g_H);
    cudaGetSymbolAddress(&pDeg, g_deg);
    cudaGetSymbolAddress(&pRow, g_rowptr);
    cudaGetSymbolAddress(&pCur, g_cursor);
    cudaGetSymbolAddress(&pSS, g_ssrc);
    cudaGetSymbolAddress(&pAgg, g_agg);
    cudaGetSymbolAddress(&pFlag, g_flag);
    cudaGetSymbolAddress(&pCtr, g_ctr);
    cudaGetSymbolAddress(&p1h, g_W1hi);
    cudaGetSymbolAddress(&p1l, g_W1lo);
    cudaGetSymbolAddress(&p2h, g_W2hi);
    cudaGetSymbolAddress(&p2l, g_W2lo);
    float* M = (float*)pM;
    float* H = (float*)pH;
    int *deg = (int*)pDeg, *rowptr = (int*)pRow, *cursor = (int*)pCur;
    int *ssrc = (int*)pSS, *agg = (int*)pAgg, *flag = (int*)pFlag;
    unsigned* ctr = (unsigned*)pCtr;
    __nv_bfloat16 *w1hi = (__nv_bfloat16*)p1h, *w1lo = (__nv_bfloat16*)p1l;
    __nv_bfloat16 *w2hi = (__nv_bfloat16*)p2h, *w2lo = (__nv_bfloat16*)p2l;

    cudaFuncSetAttribute(hmma_gemm_kernel,
                         cudaFuncAttributeMaxDynamicSharedMemorySize, SM_TOTAL);

    cudaMemsetAsync(deg, 0, N_NODES * sizeof(int));
    hist_prep_kernel<<<EDGE_GRID + WT_GRID, 256>>>(dst, deg, flag, ctr,
                                                   W1, W2, w1hi, w1lo, w2hi, w2lo);
    scan_all_kernel<<<NBLK, 256>>>(deg, rowptr, cursor, agg, flag);

    // ---- Layer 1 GEMM (embedding gather fused) ----
    hmma_gemm_kernel<<<GEMM_CTAS, 256, SM_TOTAL>>>(embed, node_id, w1hi, w1lo, norm, ctr + 0, M);

    permute_kernel<<<EDGE_GRID, 256>>>(src, dst, cursor, ssrc);
    gather_kernel<<<GATHER_BLOCKS, 256>>>(M, rowptr, deg, ssrc, norm, b1, H);

    // ---- Layer 2 ----
    hmma_gemm_kernel<<<GEMM_CTAS, 256, SM_TOTAL>>>(H, nullptr, w2hi, w2lo, norm, ctr + 1, M);
    gather_kernel<<<GATHER_BLOCKS, 256>>>(M, rowptr, deg, ssrc, norm, b2, out);
}